// round 15
// baseline (speedup 1.0000x reference)
#include <cuda_runtime.h>
#include <cuda_fp16.h>

#define N_NODES  50000
#define N_EDGES  800000
#define N_GRAPHS 256
#define DF       128
#define NHID     256
#define NOUT     768
#define SCAN_C   4096
#define SCAN_B   ((N_NODES + SCAN_C - 1) / SCAN_C)   // 13

// ---------------- scratch (device globals: no allocs allowed) ----------------
// g_deg relies on static zero-init for the first run; k_scan23 re-zeroes it
// after consuming it, so every execution leaves it zeroed for the next replay.
__device__ uint4  g_h16[N_NODES * DF / 8]; // layer features, fp16
__device__ uint2  g_y16[N_NODES * DF / 4]; // dinv-scaled GEMM out, fp16
__device__ __half g_w16[3 * DF * DF];      // W1..W3, fp16, transposed [n][k]
__device__ int    g_deg[N_NODES];          // zero-init; restored to 0 each run
__device__ int    g_rowptr[N_NODES + 1];
__device__ int    g_cur[N_NODES];
__device__ int    g_eidx[N_EDGES];         // CSR-by-dst: src node ids
__device__ float  g_dinv[N_NODES];
__device__ int    g_gbeg[N_GRAPHS + 1];    // graph start offsets in sorted batch
__device__ int    g_part[64];
__device__ int    g_is64;                  // 1 if indices are int64, 0 if int32

// low-word read: node ids fit in 32 bits; int64 is little-endian on this host
__device__ __forceinline__ int idx_lo(const void* p, long long i, int is64) {
    return is64 ? ((const int*)p)[2 * i] : ((const int*)p)[i];
}

// ---------------- W pre-convert + dtype detect (fused) ----------------
// blocks 0..191: W fp32 [k][n] -> fp16 transposed [n][k]; block 192: detect.
__global__ void k_pre(const float* __restrict__ W1,
                      const float* __restrict__ W2,
                      const float* __restrict__ W3,
                      const void* __restrict__ ei) {
    if (blockIdx.x < 192) {
        int e = blockIdx.x * 256 + threadIdx.x;    // 3*16384 total
        int m = e >> 14, r = e & 16383;
        int k = r >> 7, n = r & 127;
        const float* W = (m == 0) ? W1 : ((m == 1) ? W2 : W3);
        g_w16[m * 16384 + n * 128 + k] = __float2half(W[k * 128 + n]);
    } else {
        // interpret first 512 slots as int64; int32 data misread this way has
        // a random high word -> out of range with overwhelming probability.
        if (threadIdx.x == 0) g_is64 = 1;
        __syncthreads();
        long long v0 = ((const long long*)ei)[threadIdx.x * 2];
        long long v1 = ((const long long*)ei)[threadIdx.x * 2 + 1];
        if (v0 < 0 || v0 >= N_NODES || v1 < 0 || v1 >= N_NODES)
            atomicAnd(&g_is64, 0);
    }
}

// ---------------- graph preprocessing ----------------
__global__ void k_deg(const void* __restrict__ ei) {
    int e = blockIdx.x * blockDim.x + threadIdx.x;
    if (e < N_EDGES) {
        int d = idx_lo(ei, (long long)N_EDGES + e, g_is64);   // dst
        atomicAdd(&g_deg[d], 1);
    }
}

// 4-wide warp-shuffle inclusive scan: 4096 nodes per block (int4 loads)
__global__ void k_scan1() {
    __shared__ int ws[32];
    int tid = threadIdx.x, lane = tid & 31, wid = tid >> 5;
    int i4 = blockIdx.x * 1024 + tid;               // int4 slot
    int4 d = make_int4(0, 0, 0, 0);
    if (i4 * 4 < N_NODES) d = ((const int4*)g_deg)[i4];   // N_NODES % 4 == 0
    int p0 = d.x, p1 = p0 + d.y, p2 = p1 + d.z, p3 = p2 + d.w;
    int val = p3;
    #pragma unroll
    for (int off = 1; off < 32; off <<= 1) {
        int n = __shfl_up_sync(0xffffffffu, val, off);
        if (lane >= off) val += n;
    }
    int wbase = val - p3;                            // exclusive within warp
    if (lane == 31) ws[wid] = val;
    __syncthreads();
    if (wid == 0) {
        int s = ws[lane];
        #pragma unroll
        for (int off = 1; off < 32; off <<= 1) {
            int n = __shfl_up_sync(0xffffffffu, s, off);
            if (lane >= off) s += n;
        }
        ws[lane] = s;
    }
    __syncthreads();
    int off = wbase + ((wid > 0) ? ws[wid - 1] : 0); // exclusive thread base
    int i0 = i4 * 4;
    if (i0 < N_NODES)     g_rowptr[i0 + 1] = off + p0;
    if (i0 + 1 < N_NODES) g_rowptr[i0 + 2] = off + p1;
    if (i0 + 2 < N_NODES) g_rowptr[i0 + 3] = off + p2;
    if (i0 + 3 < N_NODES) g_rowptr[i0 + 4] = off + p3;
    if (tid == 1023) g_part[blockIdx.x] = ws[31];    // block total
}

// fused: partial-prefix (parallel) + rowptr finalize + cur + dinv + deg reset
// + graph boundaries via coalesced adjacent-difference on sorted batch.
__global__ void k_scan23(const void* __restrict__ batch) {
    __shared__ int base;
    int i = blockIdx.x * 256 + threadIdx.x;
    int is64 = g_is64;
    if (threadIdx.x < 32) {
        int c = blockIdx.x >> 4;                     // chunk index (<=12)
        int v = (threadIdx.x < c) ? g_part[threadIdx.x] : 0;
        #pragma unroll
        for (int off = 16; off; off >>= 1)
            v += __shfl_down_sync(0xffffffffu, v, off);
        if (threadIdx.x == 0) base = v;
    }
    // graph boundaries: coalesced reads, no dependence chains.
    if (i < N_NODES) {
        int b0 = idx_lo(batch, i, is64);
        int bp = (i > 0) ? idx_lo(batch, i - 1, is64) : -1;
        for (int g = bp + 1; g <= b0; g++) g_gbeg[g] = i;       // usually 0-1 iters
        if (i == N_NODES - 1)
            for (int g = b0 + 1; g <= N_GRAPHS; g++) g_gbeg[g] = N_NODES;
    }
    __syncthreads();
    if (i == 0) g_rowptr[0] = 0;
    if (i < N_NODES) {
        int d  = g_deg[i];
        g_deg[i] = 0;                                // reset for next replay
        int rp = g_rowptr[i + 1] + base;
        g_rowptr[i + 1] = rp;
        g_cur[i]  = rp - d;
        g_dinv[i] = rsqrtf((float)(d + 1));          // +1 self loop; always > 0
    }
}

__global__ void k_fill(const void* __restrict__ ei) {
    int e = blockIdx.x * blockDim.x + threadIdx.x;
    if (e < N_EDGES) {
        int is64 = g_is64;
        int s = idx_lo(ei, e, is64);                          // src
        int d = idx_lo(ei, (long long)N_EDGES + e, is64);     // dst
        int pos = atomicAdd(&g_cur[d], 1);
        g_eidx[pos] = s;
    }
}

// ---------------- tensor-core GEMM (fp16 m16n8k16 mma.sync, fp32 accum) ------
// y16[v,:] = fp16( (X @ W)[v,:] * dinv[v] ).  B pre-converted fp16 in g_w16.
#define PA 72   // halves pitch
#define PB 72

__device__ __forceinline__ void mma_f16(float* d,
                                        const unsigned* a, const unsigned* b,
                                        const float* c) {
    asm volatile(
        "mma.sync.aligned.m16n8k16.row.col.f32.f16.f16.f32 "
        "{%0,%1,%2,%3}, {%4,%5,%6,%7}, {%8,%9}, {%10,%11,%12,%13};\n"
        : "=f"(d[0]), "=f"(d[1]), "=f"(d[2]), "=f"(d[3])
        : "r"(a[0]), "r"(a[1]), "r"(a[2]), "r"(a[3]),
          "r"(b[0]), "r"(b[1]),
          "f"(c[0]), "f"(c[1]), "f"(c[2]), "f"(c[3]));
}

__global__ void __launch_bounds__(256) k_gemm_h(const float* __restrict__ Xf,
                                                int use_h16, int widx) {
    __shared__ __half As[128 * PA];
    __shared__ __half Bs[128 * PB];
    int tid  = threadIdx.x;
    int wid  = tid >> 5, lane = tid & 31;
    int wm   = wid >> 1, wn = wid & 1;       // 4 x 2 warps
    int grp  = lane >> 2, tig = lane & 3;
    int row0 = blockIdx.x * 128;
    const uint4* wt4 = (const uint4*)&g_w16[widx * 16384];

    float acc[2][8][4] = {};

    for (int kt = 0; kt < 128; kt += 64) {
        // ---- A tile: 128 rows x 64 halves ----
        if (use_h16) {
            #pragma unroll
            for (int i = 0; i < 4; i++) {
                int idx = tid + i * 256;          // 1024 uint4
                int r = idx >> 3, q = idx & 7;
                int grow = row0 + r;
                uint4 u = (grow < N_NODES) ? g_h16[grow * 16 + (kt >> 3) + q]
                                           : make_uint4(0, 0, 0, 0);
                *(uint4*)&As[r * PA + q * 8] = u;
            }
        } else {
            #pragma unroll
            for (int i = 0; i < 4; i++) {
                int idx = tid + i * 256;
                int r = idx >> 3, q = idx & 7;
                int grow = row0 + r;
                uint4 u = make_uint4(0, 0, 0, 0);
                if (grow < N_NODES) {
                    const float4* xp = (const float4*)&Xf[grow * 128 + kt + q * 8];
                    float4 f0 = xp[0], f1 = xp[1];
                    *(__half2*)&u.x = __floats2half2_rn(f0.x, f0.y);
                    *(__half2*)&u.y = __floats2half2_rn(f0.z, f0.w);
                    *(__half2*)&u.z = __floats2half2_rn(f1.x, f1.y);
                    *(__half2*)&u.w = __floats2half2_rn(f1.z, f1.w);
                }
                *(uint4*)&As[r * PA + q * 8] = u;
            }
        }
        // ---- B tile: straight fp16 copy from pre-transposed g_w16 ----
        #pragma unroll
        for (int i = 0; i < 4; i++) {
            int idx = tid + i * 256;              // 1024 uint4
            int n = idx >> 3, q = idx & 7;
            uint4 u = wt4[n * 16 + (kt >> 3) + q];
            *(uint4*)&Bs[n * PB + q * 8] = u;
        }
        __syncthreads();

        #pragma unroll
        for (int ka = 0; ka < 4; ka++) {
            int kb = ka * 16;
            unsigned a[2][4], bf[8][2];
            #pragma unroll
            for (int m = 0; m < 2; m++) {
                int r = wm * 32 + m * 16 + grp;
                a[m][0] = *(unsigned*)&As[r * PA + kb + 2 * tig];
                a[m][1] = *(unsigned*)&As[(r + 8) * PA + kb + 2 * tig];
                a[m][2] = *(unsigned*)&As[r * PA + kb + 8 + 2 * tig];
                a[m][3] = *(unsigned*)&As[(r + 8) * PA + kb + 8 + 2 * tig];
            }
            #pragma unroll
            for (int n = 0; n < 8; n++) {
                int cn = wn * 64 + n * 8 + grp;
                bf[n][0] = *(unsigned*)&Bs[cn * PB + kb + 2 * tig];
                bf[n][1] = *(unsigned*)&Bs[cn * PB + kb + 8 + 2 * tig];
            }
            #pragma unroll
            for (int m = 0; m < 2; m++)
                #pragma unroll
                for (int n = 0; n < 8; n++)
                    mma_f16(acc[m][n], a[m], bf[n], acc[m][n]);
        }
        __syncthreads();
    }

    // epilogue: scale by dinv, fp16 half2 stores
    __half2* yp = (__half2*)g_y16;
    #pragma unroll
    for (int m = 0; m < 2; m++) {
        #pragma unroll
        for (int hf = 0; hf < 2; hf++) {
            int row = row0 + wm * 32 + m * 16 + grp + hf * 8;
            if (row < N_NODES) {
                float dv = g_dinv[row];
                #pragma unroll
                for (int n = 0; n < 8; n++) {
                    int col = wn * 64 + n * 8 + 2 * tig;
                    yp[row * 64 + (col >> 1)] =
                        __floats2half2_rn(acc[m][n][hf * 2] * dv,
                                          acc[m][n][hf * 2 + 1] * dv);
                }
            }
        }
    }
}

// ---------------- gather-sum: warp/node, 32 lanes x uint2, 4-deep unroll -----
__device__ __forceinline__ void acc_row(float4& a, uint2 raw) {
    float2 lo = __half22float2(*(__half2*)&raw.x);
    float2 hi = __half22float2(*(__half2*)&raw.y);
    a.x += lo.x; a.y += lo.y; a.z += hi.x; a.w += hi.y;
}

__global__ void k_gather(const float* __restrict__ b, int relu) {
    int t = blockIdx.x * blockDim.x + threadIdx.x;
    int v = t >> 5;
    int lane = t & 31;
    if (v >= N_NODES) return;
    const uint2* yp = (const uint2*)g_y16;
    float4 acc = make_float4(0.f, 0.f, 0.f, 0.f);
    acc_row(acc, __ldg(&yp[v * 32 + lane]));        // self loop
    int e = g_rowptr[v], end = g_rowptr[v + 1];
    for (; e + 3 < end; e += 4) {                   // 4 rows in flight
        int s0 = g_eidx[e],     s1 = g_eidx[e + 1];
        int s2 = g_eidx[e + 2], s3 = g_eidx[e + 3];
        uint2 r0 = __ldg(&yp[s0 * 32 + lane]);
        uint2 r1 = __ldg(&yp[s1 * 32 + lane]);
        uint2 r2 = __ldg(&yp[s2 * 32 + lane]);
        uint2 r3 = __ldg(&yp[s3 * 32 + lane]);
        acc_row(acc, r0); acc_row(acc, r1);
        acc_row(acc, r2); acc_row(acc, r3);
    }
    for (; e < end; e++) acc_row(acc, __ldg(&yp[g_eidx[e] * 32 + lane]));

    float dv = g_dinv[v];
    float4 bb = ((const float4*)b)[lane];
    float o0 = dv * acc.x + bb.x, o1 = dv * acc.y + bb.y;
    float o2 = dv * acc.z + bb.z, o3 = dv * acc.w + bb.w;
    if (relu) {
        o0 = fmaxf(o0, 0.f); o1 = fmaxf(o1, 0.f);
        o2 = fmaxf(o2, 0.f); o3 = fmaxf(o3, 0.f);
    }
    uint2 w;
    *(__half2*)&w.x = __floats2half2_rn(o0, o1);
    *(__half2*)&w.y = __floats2half2_rn(o2, o3);
    ((uint2*)g_h16)[v * 32 + lane] = w;
}

// ---------------- fused tail: mean-pool + MLP1 + MLP2 (4 graphs / block) -----
__global__ void __launch_bounds__(768) k_tail(const float* __restrict__ Wm1,
                                              const float* __restrict__ bm1,
                                              const float* __restrict__ Wm2,
                                              const float* __restrict__ bm2,
                                              float* __restrict__ out) {
    __shared__ float p[4][DF];
    __shared__ float q[4][NHID];
    int g0 = blockIdx.x * 4;
    int tid = threadIdx.x;

    // phase 1: mean pool (512 threads: 4 graphs x 128 dims); bounds precomputed
    if (tid < 512) {
        int gl = tid >> 7, dim = tid & 127;
        int g = g0 + gl;
        int beg = g_gbeg[g], end = g_gbeg[g + 1];
        const __half* hp = (const __half*)g_h16;
        float acc = 0.f;
        for (int v = beg; v < end; v++) acc += __half2float(hp[v * DF + dim]);
        p[gl][dim] = (end > beg) ? acc / (float)(end - beg) : 0.f;
    }
    __syncthreads();

    // phase 2: MLP1 (256 threads, 4 graphs each)
    if (tid < NHID) {
        int j = tid;
        float bias = bm1[j];
        float a0 = bias, a1 = bias, a2 = bias, a3 = bias;
        #pragma unroll 4
        for (int k = 0; k < DF; k++) {
            float w = Wm1[k * NHID + j];
            a0 += p[0][k] * w; a1 += p[1][k] * w;
            a2 += p[2][k] * w; a3 += p[3][k] * w;
        }
        q[0][j] = fmaxf(a0, 0.f); q[1][j] = fmaxf(a1, 0.f);
        q[2][j] = fmaxf(a2, 0.f); q[3][j] = fmaxf(a3, 0.f);
    }
    __syncthreads();

    // phase 3: MLP2 (768 threads, 4 graphs each)
    {
        int j = tid;
        float bias = bm2[j];
        float a0 = bias, a1 = bias, a2 = bias, a3 = bias;
        #pragma unroll 4
        for (int k = 0; k < NHID; k++) {
            float w = Wm2[k * NOUT + j];
            a0 += q[0][k] * w; a1 += q[1][k] * w;
            a2 += q[2][k] * w; a3 += q[3][k] * w;
        }
        out[(g0 + 0) * NOUT + j] = a0;
        out[(g0 + 1) * NOUT + j] = a1;
        out[(g0 + 2) * NOUT + j] = a2;
        out[(g0 + 3) * NOUT + j] = a3;
    }
}

// ---------------- launch ----------------
extern "C" void kernel_launch(void* const* d_in, const int* in_sizes, int n_in,
                              void* d_out, int out_size) {
    const float* x     = (const float*)d_in[0];
    const void*  ei    = d_in[1];        // int32 or int64, detected on device
    const void*  batch = d_in[2];
    const float* W1  = (const float*)d_in[3];
    const float* b1  = (const float*)d_in[4];
    const float* W2  = (const float*)d_in[5];
    const float* b2  = (const float*)d_in[6];
    const float* W3  = (const float*)d_in[7];
    const float* b3  = (const float*)d_in[8];
    const float* Wm1 = (const float*)d_in[9];
    const float* bm1 = (const float*)d_in[10];
    const float* Wm2 = (const float*)d_in[11];
    const float* bm2 = (const float*)d_in[12];
    float* out = (float*)d_out;

    const int ZB = (N_NODES + 255) / 256;
    const int EB = (N_EDGES + 255) / 256;
    const int GB = (N_NODES + 127) / 128;        // gemm row tiles
    const int WB = (N_NODES * 32 + 255) / 256;   // warp-per-node kernels

    // preprocessing (g_deg arrives zeroed: static init / reset by k_scan23)
    k_pre   <<<193, 256>>>(W1, W2, W3, ei);      // W->fp16 transpose + detect
    k_deg   <<<EB, 256>>>(ei);
    k_scan1 <<<SCAN_B, 1024>>>();
    k_scan23<<<ZB, 256>>>(batch);  // prefix + rowptr + cur + dinv + deg=0 + gbounds
    k_fill  <<<EB, 256>>>(ei);

    // layer 1
    k_gemm_h<<<GB, 256>>>(x, 0, 0);
    k_gather<<<WB, 256>>>(b1, 1);
    // layer 2
    k_gemm_h<<<GB, 256>>>(nullptr, 1, 1);
    k_gather<<<WB, 256>>>(b2, 1);
    // layer 3 (no relu)
    k_gemm_h<<<GB, 256>>>(nullptr, 1, 2);
    k_gather<<<WB, 256>>>(b3, 0);

    // fused pooling + MLP head
    k_tail<<<N_GRAPHS / 4, 768>>>(Wm1, bm1, Wm2, bm2, out);
}

// round 16
// speedup vs baseline: 1.4319x; 1.4319x over previous
#include <cuda_runtime.h>
#include <cuda_fp16.h>

#define N_NODES  50000
#define N_EDGES  800000
#define N_GRAPHS 256
#define DF       128
#define NHID     256
#define NOUT     768
#define SCAN_C   4096
#define SCAN_B   ((N_NODES + SCAN_C - 1) / SCAN_C)   // 13

// ---------------- scratch (device globals: no allocs allowed) ----------------
// g_deg relies on static zero-init for the first run; k_scan23 re-zeroes it
// after consuming it, so every execution leaves it zeroed for the next replay.
__device__ uint4  g_h16[N_NODES * DF / 8]; // layer features, fp16
__device__ uint2  g_y16[N_NODES * DF / 4]; // dinv-scaled GEMM out, fp16
__device__ __half g_w16[3 * DF * DF];      // W1..W3, fp16, transposed [n][k]
__device__ int    g_deg[N_NODES];          // zero-init; restored to 0 each run
__device__ int    g_rowptr[N_NODES + 1];
__device__ int    g_cur[N_NODES];
__device__ int    g_eidx[N_EDGES];         // CSR-by-dst: src node ids
__device__ float  g_dinv[N_NODES];
__device__ int    g_gbeg[N_GRAPHS + 1];    // graph start offsets in sorted batch
__device__ int    g_part[64];
__device__ int    g_is64;                  // 1 if indices are int64, 0 if int32

// low-word read: node ids fit in 32 bits; int64 is little-endian on this host
__device__ __forceinline__ int idx_lo(const void* p, long long i, int is64) {
    return is64 ? ((const int*)p)[2 * i] : ((const int*)p)[i];
}

// ---------------- W pre-convert + dtype detect (fused) ----------------
// blocks 0..191: W fp32 [k][n] -> fp16 transposed [n][k]; block 192: detect.
__global__ void k_pre(const float* __restrict__ W1,
                      const float* __restrict__ W2,
                      const float* __restrict__ W3,
                      const void* __restrict__ ei) {
    if (blockIdx.x < 192) {
        int e = blockIdx.x * 256 + threadIdx.x;    // 3*16384 total
        int m = e >> 14, r = e & 16383;
        int k = r >> 7, n = r & 127;
        const float* W = (m == 0) ? W1 : ((m == 1) ? W2 : W3);
        g_w16[m * 16384 + n * 128 + k] = __float2half(W[k * 128 + n]);
    } else {
        // interpret first 512 slots as int64; int32 data misread this way has
        // a random high word -> out of range with overwhelming probability.
        if (threadIdx.x == 0) g_is64 = 1;
        __syncthreads();
        long long v0 = ((const long long*)ei)[threadIdx.x * 2];
        long long v1 = ((const long long*)ei)[threadIdx.x * 2 + 1];
        if (v0 < 0 || v0 >= N_NODES || v1 < 0 || v1 >= N_NODES)
            atomicAnd(&g_is64, 0);
    }
}

// ---------------- degree histogram + graph boundaries (fused) ----------------
// boundary detection: batch is sorted, so g_gbeg[g] = first i with batch[i]==g,
// found by coalesced adjacent-difference. Rides along with the atomics.
__global__ void k_deg(const void* __restrict__ ei, const void* __restrict__ batch) {
    int e = blockIdx.x * blockDim.x + threadIdx.x;
    int is64 = g_is64;
    if (e < N_EDGES) {
        int d = idx_lo(ei, (long long)N_EDGES + e, is64);     // dst
        atomicAdd(&g_deg[d], 1);
    }
    if (e < N_NODES) {
        int b0 = idx_lo(batch, e, is64);
        int bp = (e > 0) ? idx_lo(batch, e - 1, is64) : -1;
        for (int g = bp + 1; g <= b0; g++) g_gbeg[g] = e;     // usually 0-1 iters
        if (e == N_NODES - 1)
            for (int g = b0 + 1; g <= N_GRAPHS; g++) g_gbeg[g] = N_NODES;
    }
}

// 4-wide warp-shuffle inclusive scan: 4096 nodes per block (int4 loads)
__global__ void k_scan1() {
    __shared__ int ws[32];
    int tid = threadIdx.x, lane = tid & 31, wid = tid >> 5;
    int i4 = blockIdx.x * 1024 + tid;               // int4 slot
    int4 d = make_int4(0, 0, 0, 0);
    if (i4 * 4 < N_NODES) d = ((const int4*)g_deg)[i4];   // N_NODES % 4 == 0
    int p0 = d.x, p1 = p0 + d.y, p2 = p1 + d.z, p3 = p2 + d.w;
    int val = p3;
    #pragma unroll
    for (int off = 1; off < 32; off <<= 1) {
        int n = __shfl_up_sync(0xffffffffu, val, off);
        if (lane >= off) val += n;
    }
    int wbase = val - p3;                            // exclusive within warp
    if (lane == 31) ws[wid] = val;
    __syncthreads();
    if (wid == 0) {
        int s = ws[lane];
        #pragma unroll
        for (int off = 1; off < 32; off <<= 1) {
            int n = __shfl_up_sync(0xffffffffu, s, off);
            if (lane >= off) s += n;
        }
        ws[lane] = s;
    }
    __syncthreads();
    int off = wbase + ((wid > 0) ? ws[wid - 1] : 0); // exclusive thread base
    int i0 = i4 * 4;
    if (i0 < N_NODES)     g_rowptr[i0 + 1] = off + p0;
    if (i0 + 1 < N_NODES) g_rowptr[i0 + 2] = off + p1;
    if (i0 + 2 < N_NODES) g_rowptr[i0 + 3] = off + p2;
    if (i0 + 3 < N_NODES) g_rowptr[i0 + 4] = off + p3;
    if (tid == 1023) g_part[blockIdx.x] = ws[31];    // block total
}

// fused: partial-prefix (parallel) + rowptr finalize + cur + dinv + deg reset
__global__ void k_scan23() {
    __shared__ int base;
    int i = blockIdx.x * 256 + threadIdx.x;
    if (threadIdx.x < 32) {
        int c = blockIdx.x >> 4;                     // chunk index (<=12)
        int v = (threadIdx.x < c) ? g_part[threadIdx.x] : 0;
        #pragma unroll
        for (int off = 16; off; off >>= 1)
            v += __shfl_down_sync(0xffffffffu, v, off);
        if (threadIdx.x == 0) base = v;
    }
    __syncthreads();
    if (i == 0) g_rowptr[0] = 0;
    if (i < N_NODES) {
        int d  = g_deg[i];
        g_deg[i] = 0;                                // reset for next replay
        int rp = g_rowptr[i + 1] + base;
        g_rowptr[i + 1] = rp;
        g_cur[i]  = rp - d;
        g_dinv[i] = rsqrtf((float)(d + 1));          // +1 self loop; always > 0
    }
}

__global__ void k_fill(const void* __restrict__ ei) {
    int e = blockIdx.x * blockDim.x + threadIdx.x;
    if (e < N_EDGES) {
        int is64 = g_is64;
        int s = idx_lo(ei, e, is64);                          // src
        int d = idx_lo(ei, (long long)N_EDGES + e, is64);     // dst
        int pos = atomicAdd(&g_cur[d], 1);
        g_eidx[pos] = s;
    }
}

// ---------------- tensor-core GEMM (fp16 m16n8k16 mma.sync, fp32 accum) ------
// y16[v,:] = fp16( (X @ W)[v,:] * dinv[v] ).  B pre-converted fp16 in g_w16.
#define PA 72   // halves pitch
#define PB 72

__device__ __forceinline__ void mma_f16(float* d,
                                        const unsigned* a, const unsigned* b,
                                        const float* c) {
    asm volatile(
        "mma.sync.aligned.m16n8k16.row.col.f32.f16.f16.f32 "
        "{%0,%1,%2,%3}, {%4,%5,%6,%7}, {%8,%9}, {%10,%11,%12,%13};\n"
        : "=f"(d[0]), "=f"(d[1]), "=f"(d[2]), "=f"(d[3])
        : "r"(a[0]), "r"(a[1]), "r"(a[2]), "r"(a[3]),
          "r"(b[0]), "r"(b[1]),
          "f"(c[0]), "f"(c[1]), "f"(c[2]), "f"(c[3]));
}

__global__ void __launch_bounds__(256) k_gemm_h(const float* __restrict__ Xf,
                                                int use_h16, int widx) {
    __shared__ __half As[128 * PA];
    __shared__ __half Bs[128 * PB];
    int tid  = threadIdx.x;
    int wid  = tid >> 5, lane = tid & 31;
    int wm   = wid >> 1, wn = wid & 1;       // 4 x 2 warps
    int grp  = lane >> 2, tig = lane & 3;
    int row0 = blockIdx.x * 128;
    const uint4* wt4 = (const uint4*)&g_w16[widx * 16384];

    float acc[2][8][4] = {};

    for (int kt = 0; kt < 128; kt += 64) {
        // ---- A tile: 128 rows x 64 halves ----
        if (use_h16) {
            #pragma unroll
            for (int i = 0; i < 4; i++) {
                int idx = tid + i * 256;          // 1024 uint4
                int r = idx >> 3, q = idx & 7;
                int grow = row0 + r;
                uint4 u = (grow < N_NODES) ? g_h16[grow * 16 + (kt >> 3) + q]
                                           : make_uint4(0, 0, 0, 0);
                *(uint4*)&As[r * PA + q * 8] = u;
            }
        } else {
            #pragma unroll
            for (int i = 0; i < 4; i++) {
                int idx = tid + i * 256;
                int r = idx >> 3, q = idx & 7;
                int grow = row0 + r;
                uint4 u = make_uint4(0, 0, 0, 0);
                if (grow < N_NODES) {
                    const float4* xp = (const float4*)&Xf[grow * 128 + kt + q * 8];
                    float4 f0 = xp[0], f1 = xp[1];
                    *(__half2*)&u.x = __floats2half2_rn(f0.x, f0.y);
                    *(__half2*)&u.y = __floats2half2_rn(f0.z, f0.w);
                    *(__half2*)&u.z = __floats2half2_rn(f1.x, f1.y);
                    *(__half2*)&u.w = __floats2half2_rn(f1.z, f1.w);
                }
                *(uint4*)&As[r * PA + q * 8] = u;
            }
        }
        // ---- B tile: straight fp16 copy from pre-transposed g_w16 ----
        #pragma unroll
        for (int i = 0; i < 4; i++) {
            int idx = tid + i * 256;              // 1024 uint4
            int n = idx >> 3, q = idx & 7;
            uint4 u = wt4[n * 16 + (kt >> 3) + q];
            *(uint4*)&Bs[n * PB + q * 8] = u;
        }
        __syncthreads();

        #pragma unroll
        for (int ka = 0; ka < 4; ka++) {
            int kb = ka * 16;
            unsigned a[2][4], bf[8][2];
            #pragma unroll
            for (int m = 0; m < 2; m++) {
                int r = wm * 32 + m * 16 + grp;
                a[m][0] = *(unsigned*)&As[r * PA + kb + 2 * tig];
                a[m][1] = *(unsigned*)&As[(r + 8) * PA + kb + 2 * tig];
                a[m][2] = *(unsigned*)&As[r * PA + kb + 8 + 2 * tig];
                a[m][3] = *(unsigned*)&As[(r + 8) * PA + kb + 8 + 2 * tig];
            }
            #pragma unroll
            for (int n = 0; n < 8; n++) {
                int cn = wn * 64 + n * 8 + grp;
                bf[n][0] = *(unsigned*)&Bs[cn * PB + kb + 2 * tig];
                bf[n][1] = *(unsigned*)&Bs[cn * PB + kb + 8 + 2 * tig];
            }
            #pragma unroll
            for (int m = 0; m < 2; m++)
                #pragma unroll
                for (int n = 0; n < 8; n++)
                    mma_f16(acc[m][n], a[m], bf[n], acc[m][n]);
        }
        __syncthreads();
    }

    // epilogue: scale by dinv, fp16 half2 stores
    __half2* yp = (__half2*)g_y16;
    #pragma unroll
    for (int m = 0; m < 2; m++) {
        #pragma unroll
        for (int hf = 0; hf < 2; hf++) {
            int row = row0 + wm * 32 + m * 16 + grp + hf * 8;
            if (row < N_NODES) {
                float dv = g_dinv[row];
                #pragma unroll
                for (int n = 0; n < 8; n++) {
                    int col = wn * 64 + n * 8 + 2 * tig;
                    yp[row * 64 + (col >> 1)] =
                        __floats2half2_rn(acc[m][n][hf * 2] * dv,
                                          acc[m][n][hf * 2 + 1] * dv);
                }
            }
        }
    }
}

// ---------------- gather-sum: warp/node, 32 lanes x uint2, 4-deep unroll -----
__device__ __forceinline__ void acc_row(float4& a, uint2 raw) {
    float2 lo = __half22float2(*(__half2*)&raw.x);
    float2 hi = __half22float2(*(__half2*)&raw.y);
    a.x += lo.x; a.y += lo.y; a.z += hi.x; a.w += hi.y;
}

__global__ void k_gather(const float* __restrict__ b, int relu) {
    int t = blockIdx.x * blockDim.x + threadIdx.x;
    int v = t >> 5;
    int lane = t & 31;
    if (v >= N_NODES) return;
    const uint2* yp = (const uint2*)g_y16;
    float4 acc = make_float4(0.f, 0.f, 0.f, 0.f);
    acc_row(acc, __ldg(&yp[v * 32 + lane]));        // self loop
    int e = g_rowptr[v], end = g_rowptr[v + 1];
    for (; e + 3 < end; e += 4) {                   // 4 rows in flight
        int s0 = g_eidx[e],     s1 = g_eidx[e + 1];
        int s2 = g_eidx[e + 2], s3 = g_eidx[e + 3];
        uint2 r0 = __ldg(&yp[s0 * 32 + lane]);
        uint2 r1 = __ldg(&yp[s1 * 32 + lane]);
        uint2 r2 = __ldg(&yp[s2 * 32 + lane]);
        uint2 r3 = __ldg(&yp[s3 * 32 + lane]);
        acc_row(acc, r0); acc_row(acc, r1);
        acc_row(acc, r2); acc_row(acc, r3);
    }
    for (; e < end; e++) acc_row(acc, __ldg(&yp[g_eidx[e] * 32 + lane]));

    float dv = g_dinv[v];
    float4 bb = ((const float4*)b)[lane];
    float o0 = dv * acc.x + bb.x, o1 = dv * acc.y + bb.y;
    float o2 = dv * acc.z + bb.z, o3 = dv * acc.w + bb.w;
    if (relu) {
        o0 = fmaxf(o0, 0.f); o1 = fmaxf(o1, 0.f);
        o2 = fmaxf(o2, 0.f); o3 = fmaxf(o3, 0.f);
    }
    uint2 w;
    *(__half2*)&w.x = __floats2half2_rn(o0, o1);
    *(__half2*)&w.y = __floats2half2_rn(o2, o3);
    ((uint2*)g_h16)[v * 32 + lane] = w;
}

// ---------------- fused tail: mean-pool + MLP1 + MLP2 (4 graphs / block) -----
__global__ void __launch_bounds__(768) k_tail(const float* __restrict__ Wm1,
                                              const float* __restrict__ bm1,
                                              const float* __restrict__ Wm2,
                                              const float* __restrict__ bm2,
                                              float* __restrict__ out) {
    __shared__ float p[4][DF];
    __shared__ float q[4][NHID];
    int g0 = blockIdx.x * 4;
    int tid = threadIdx.x;

    // phase 1: mean pool (512 threads: 4 graphs x 128 dims); bounds precomputed
    if (tid < 512) {
        int gl = tid >> 7, dim = tid & 127;
        int g = g0 + gl;
        int beg = g_gbeg[g], end = g_gbeg[g + 1];
        const __half* hp = (const __half*)g_h16;
        float acc = 0.f;
        for (int v = beg; v < end; v++) acc += __half2float(hp[v * DF + dim]);
        p[gl][dim] = (end > beg) ? acc / (float)(end - beg) : 0.f;
    }
    __syncthreads();

    // phase 2: MLP1 (256 threads, 4 graphs each)
    if (tid < NHID) {
        int j = tid;
        float bias = bm1[j];
        float a0 = bias, a1 = bias, a2 = bias, a3 = bias;
        #pragma unroll 4
        for (int k = 0; k < DF; k++) {
            float w = Wm1[k * NHID + j];
            a0 += p[0][k] * w; a1 += p[1][k] * w;
            a2 += p[2][k] * w; a3 += p[3][k] * w;
        }
        q[0][j] = fmaxf(a0, 0.f); q[1][j] = fmaxf(a1, 0.f);
        q[2][j] = fmaxf(a2, 0.f); q[3][j] = fmaxf(a3, 0.f);
    }
    __syncthreads();

    // phase 3: MLP2 (768 threads, 4 graphs each)
    {
        int j = tid;
        float bias = bm2[j];
        float a0 = bias, a1 = bias, a2 = bias, a3 = bias;
        #pragma unroll 4
        for (int k = 0; k < NHID; k++) {
            float w = Wm2[k * NOUT + j];
            a0 += q[0][k] * w; a1 += q[1][k] * w;
            a2 += q[2][k] * w; a3 += q[3][k] * w;
        }
        out[(g0 + 0) * NOUT + j] = a0;
        out[(g0 + 1) * NOUT + j] = a1;
        out[(g0 + 2) * NOUT + j] = a2;
        out[(g0 + 3) * NOUT + j] = a3;
    }
}

// ---------------- launch ----------------
extern "C" void kernel_launch(void* const* d_in, const int* in_sizes, int n_in,
                              void* d_out, int out_size) {
    const float* x     = (const float*)d_in[0];
    const void*  ei    = d_in[1];        // int32 or int64, detected on device
    const void*  batch = d_in[2];
    const float* W1  = (const float*)d_in[3];
    const float* b1  = (const float*)d_in[4];
    const float* W2  = (const float*)d_in[5];
    const float* b2  = (const float*)d_in[6];
    const float* W3  = (const float*)d_in[7];
    const float* b3  = (const float*)d_in[8];
    const float* Wm1 = (const float*)d_in[9];
    const float* bm1 = (const float*)d_in[10];
    const float* Wm2 = (const float*)d_in[11];
    const float* bm2 = (const float*)d_in[12];
    float* out = (float*)d_out;

    const int ZB = (N_NODES + 255) / 256;
    const int EB = (N_EDGES + 255) / 256;
    const int GB = (N_NODES + 127) / 128;        // gemm row tiles
    const int WB = (N_NODES * 32 + 255) / 256;   // warp-per-node kernels

    // preprocessing (g_deg arrives zeroed: static init / reset by k_scan23)
    k_pre   <<<193, 256>>>(W1, W2, W3, ei);      // W->fp16 transpose + detect
    k_deg   <<<EB, 256>>>(ei, batch);            // histogram + graph bounds
    k_scan1 <<<SCAN_B, 1024>>>();
    k_scan23<<<ZB, 256>>>();             // prefix + rowptr + cur + dinv + deg=0
    k_fill  <<<EB, 256>>>(ei);

    // layer 1
    k_gemm_h<<<GB, 256>>>(x, 0, 0);
    k_gather<<<WB, 256>>>(b1, 1);
    // layer 2
    k_gemm_h<<<GB, 256>>>(nullptr, 1, 1);
    k_gather<<<WB, 256>>>(b2, 1);
    // layer 3 (no relu)
    k_gemm_h<<<GB, 256>>>(nullptr, 1, 2);
    k_gather<<<WB, 256>>>(b3, 0);

    // fused pooling + MLP head
    k_tail<<<N_GRAPHS / 4, 768>>>(Wm1, bm1, Wm2, bm2, out);
}